// round 1
// baseline (speedup 1.0000x reference)
#include <cuda_runtime.h>
#include <math.h>

// Problem constants
#define Bsz   4
#define Tn    4096
#define Dn    1024
#define Hn    8
#define HDn   128
#define MHn   2048
#define Mtok  (Bsz * Tn)          // 16384 tokens
#define EPSv  1e-6f

// ---------------------------------------------------------------------------
// Device-global scratch (no cudaMalloc allowed)
// ---------------------------------------------------------------------------
__device__ float g_wq_in[MHn * Dn];        // quantized in_proj  (2048 x 1024)
__device__ float g_wq_o [Dn  * Dn];        // quantized o_proj   (1024 x 1024)
__device__ float g_wq_mi[MHn * Dn];        // quantized mlp_in   (2048 x 1024)
__device__ float g_wq_mo[Dn  * MHn];       // quantized mlp_out  (1024 x 2048)
__device__ float g_h   [(size_t)Mtok * Dn];   // rmsnorm output (reused for h2)
__device__ float g_qkv [(size_t)Mtok * MHn];  // qkv (reused for mlp activation)
__device__ float g_gated[(size_t)Mtok * Dn];  // y * silu(gate)
__device__ float g_x2  [(size_t)Mtok * Dn];   // post-attention residual state

// ---------------------------------------------------------------------------
// Per-row int8 fake quantization: wq = round(w/scale)*scale, scale=max|row|/127
// ---------------------------------------------------------------------------
__global__ void quantize_rows_kernel(const float* __restrict__ w,
                                     float* __restrict__ wq, int C) {
    int row = blockIdx.x;
    const float* wr = w + (size_t)row * C;
    float m = 0.f;
    for (int i = threadIdx.x; i < C; i += blockDim.x)
        m = fmaxf(m, fabsf(wr[i]));

    __shared__ float sh[32];
    int lane = threadIdx.x & 31, wid = threadIdx.x >> 5;
#pragma unroll
    for (int o = 16; o; o >>= 1) m = fmaxf(m, __shfl_xor_sync(0xffffffffu, m, o));
    if (lane == 0) sh[wid] = m;
    __syncthreads();
    if (wid == 0) {
        float v = (lane < (blockDim.x >> 5)) ? sh[lane] : 0.f;
#pragma unroll
        for (int o = 16; o; o >>= 1) v = fmaxf(v, __shfl_xor_sync(0xffffffffu, v, o));
        if (lane == 0) sh[0] = v;
    }
    __syncthreads();
    float scale = fmaxf(sh[0] * (1.0f / 127.0f), 1e-8f);
    for (int i = threadIdx.x; i < C; i += blockDim.x)
        wq[(size_t)row * C + i] = rintf(wr[i] / scale) * scale;  // rint = round-half-even, matches jnp.round
}

// ---------------------------------------------------------------------------
// RMSNorm: one block per token row of Dn
// ---------------------------------------------------------------------------
__global__ void rmsnorm_kernel(const float* __restrict__ x,
                               const float* __restrict__ w,
                               float* __restrict__ out) {
    int row = blockIdx.x;
    const float* xr = x + (size_t)row * Dn;
    float ss = 0.f;
    for (int i = threadIdx.x; i < Dn; i += blockDim.x) {
        float v = xr[i];
        ss += v * v;
    }
    __shared__ float sh[32];
    int lane = threadIdx.x & 31, wid = threadIdx.x >> 5;
#pragma unroll
    for (int o = 16; o; o >>= 1) ss += __shfl_xor_sync(0xffffffffu, ss, o);
    if (lane == 0) sh[wid] = ss;
    __syncthreads();
    if (wid == 0) {
        float v = (lane < (blockDim.x >> 5)) ? sh[lane] : 0.f;
#pragma unroll
        for (int o = 16; o; o >>= 1) v += __shfl_xor_sync(0xffffffffu, v, o);
        if (lane == 0) sh[0] = v;
    }
    __syncthreads();
    float inv = rsqrtf(sh[0] * (1.0f / Dn) + EPSv);
    for (int i = threadIdx.x; i < Dn; i += blockDim.x)
        out[(size_t)row * Dn + i] = xr[i] * inv * w[i];
}

// ---------------------------------------------------------------------------
// Causal exponential-filter conv as a linear recurrence + SiLU gating.
// qkv[b,t,0:D]=signal, qkv[b,t,D:2D]=gate.  y[t]=alpha*y[t-1]+s[t], scaled f0.
// gated[b,t,c] = f0*y[t,c] * silu(gate[t,c])
// grid: Bsz * (Dn/64) blocks, 64 threads (one channel each)
// ---------------------------------------------------------------------------
__global__ void scan_gate_kernel(const float* __restrict__ qkv,
                                 const float* __restrict__ filt,   // (T, H) row-major
                                 float* __restrict__ gated) {
    int b = blockIdx.x >> 4;
    int c = ((blockIdx.x & 15) << 6) + threadIdx.x;
    int h = c >> 7;                    // c / HEAD_DIM
    float f0 = filt[h];                // filt[0, h]
    float alpha = filt[Hn + h] / f0;   // filt[1, h] / filt[0, h]
    const float* base = qkv + (size_t)b * Tn * MHn;
    float* ob = gated + (size_t)b * Tn * Dn;
    float y = 0.f;
    for (int t = 0; t < Tn; ++t) {
        float s = base[(size_t)t * MHn + c];
        float g = base[(size_t)t * MHn + Dn + c];
        y = fmaf(alpha, y, s);
        float sig = 1.0f / (1.0f + expf(-g));
        ob[(size_t)t * Dn + c] = (f0 * y) * (g * sig);
    }
}

// ---------------------------------------------------------------------------
// SGEMM: C[m,n] = sum_k A[m,k] * Bw[n,k]  (+ epilogue)
// EPI: 0 = none, 1 = C += Add (residual), 2 = exact GELU
// 128x128 tile, BK=8, 256 threads, 8x8 per-thread microtile.
// All shapes here are multiples of 128 (M=16384, N in {1024,2048}, K in {1024,2048}).
// ---------------------------------------------------------------------------
template <int EPI>
__global__ __launch_bounds__(256)
void sgemm_kernel(const float* __restrict__ A, const float* __restrict__ Bw,
                  const float* __restrict__ Add, float* __restrict__ C,
                  int M, int N, int K) {
    __shared__ float As[8][128];
    __shared__ float Bs[8][128];

    int tid = threadIdx.x;
    int bm = blockIdx.y * 128;
    int bn = blockIdx.x * 128;

    int ar = tid >> 1;            // 0..127: row within tile
    int ac = (tid & 1) << 2;      // 0 or 4: float4 column offset within BK
    const float* Ap = A  + (size_t)(bm + ar) * K + ac;
    const float* Bp = Bw + (size_t)(bn + ar) * K + ac;

    int tm0 = (tid >> 4) << 3;    // thread micro-tile origin (rows)
    int tn0 = (tid & 15) << 3;    // thread micro-tile origin (cols)

    float acc[8][8];
#pragma unroll
    for (int i = 0; i < 8; ++i)
#pragma unroll
        for (int j = 0; j < 8; ++j) acc[i][j] = 0.f;

    int KT = K >> 3;
    float4 a_next = *(const float4*)Ap;
    float4 b_next = *(const float4*)Bp;

    for (int kt = 0; kt < KT; ++kt) {
        float4 a_cur = a_next, b_cur = b_next;
        As[ac + 0][ar] = a_cur.x; As[ac + 1][ar] = a_cur.y;
        As[ac + 2][ar] = a_cur.z; As[ac + 3][ar] = a_cur.w;
        Bs[ac + 0][ar] = b_cur.x; Bs[ac + 1][ar] = b_cur.y;
        Bs[ac + 2][ar] = b_cur.z; Bs[ac + 3][ar] = b_cur.w;
        __syncthreads();

        if (kt + 1 < KT) {
            a_next = *(const float4*)(Ap + (size_t)(kt + 1) * 8);
            b_next = *(const float4*)(Bp + (size_t)(kt + 1) * 8);
        }

#pragma unroll
        for (int kk = 0; kk < 8; ++kk) {
            float4 a0 = *(const float4*)&As[kk][tm0];
            float4 a1 = *(const float4*)&As[kk][tm0 + 4];
            float4 b0 = *(const float4*)&Bs[kk][tn0];
            float4 b1 = *(const float4*)&Bs[kk][tn0 + 4];
            float af[8] = {a0.x, a0.y, a0.z, a0.w, a1.x, a1.y, a1.z, a1.w};
            float bf[8] = {b0.x, b0.y, b0.z, b0.w, b1.x, b1.y, b1.z, b1.w};
#pragma unroll
            for (int i = 0; i < 8; ++i)
#pragma unroll
                for (int j = 0; j < 8; ++j)
                    acc[i][j] = fmaf(af[i], bf[j], acc[i][j]);
        }
        __syncthreads();
    }

#pragma unroll
    for (int i = 0; i < 8; ++i) {
        int row = bm + tm0 + i;
#pragma unroll
        for (int j = 0; j < 8; ++j) {
            int col = bn + tn0 + j;
            size_t idx = (size_t)row * N + col;
            float v = acc[i][j];
            if (EPI == 1) v += Add[idx];
            if (EPI == 2) v = 0.5f * v * (1.0f + erff(v * 0.70710678118654752440f));
            C[idx] = v;
        }
    }
}

// ---------------------------------------------------------------------------
// Launch
// ---------------------------------------------------------------------------
extern "C" void kernel_launch(void* const* d_in, const int* in_sizes, int n_in,
                              void* d_out, int out_size) {
    (void)in_sizes; (void)n_in; (void)out_size;
    const float* x    = (const float*)d_in[0];
    const float* n1w  = (const float*)d_in[1];
    const float* n2w  = (const float*)d_in[2];
    const float* w_in = (const float*)d_in[3];
    const float* w_o  = (const float*)d_in[4];
    const float* w_mi = (const float*)d_in[5];
    const float* w_mo = (const float*)d_in[6];
    const float* filt = (const float*)d_in[7];
    float* out = (float*)d_out;

    float *p_wq_in, *p_wq_o, *p_wq_mi, *p_wq_mo, *p_h, *p_qkv, *p_gated, *p_x2;
    cudaGetSymbolAddress((void**)&p_wq_in, g_wq_in);
    cudaGetSymbolAddress((void**)&p_wq_o,  g_wq_o);
    cudaGetSymbolAddress((void**)&p_wq_mi, g_wq_mi);
    cudaGetSymbolAddress((void**)&p_wq_mo, g_wq_mo);
    cudaGetSymbolAddress((void**)&p_h,     g_h);
    cudaGetSymbolAddress((void**)&p_qkv,   g_qkv);
    cudaGetSymbolAddress((void**)&p_gated, g_gated);
    cudaGetSymbolAddress((void**)&p_x2,    g_x2);

    // 1) Quantize all weights
    quantize_rows_kernel<<<MHn, 256>>>(w_in, p_wq_in, Dn);
    quantize_rows_kernel<<<Dn,  256>>>(w_o,  p_wq_o,  Dn);
    quantize_rows_kernel<<<MHn, 256>>>(w_mi, p_wq_mi, Dn);
    quantize_rows_kernel<<<Dn,  256>>>(w_mo, p_wq_mo, MHn);

    // 2) h = rmsnorm(x, norm1_w)
    rmsnorm_kernel<<<Mtok, 256>>>(x, n1w, p_h);

    // 3) qkv = h @ Wq_in^T        (16384 x 2048, K=1024)
    sgemm_kernel<0><<<dim3(MHn / 128, Mtok / 128), 256>>>(p_h, p_wq_in, nullptr, p_qkv,
                                                          Mtok, MHn, Dn);

    // 4) causal exponential conv (linear recurrence) + SiLU gate
    scan_gate_kernel<<<Bsz * (Dn / 64), 64>>>(p_qkv, filt, p_gated);

    // 5) x2 = x + gated @ Wq_o^T  (16384 x 1024, K=1024)
    sgemm_kernel<1><<<dim3(Dn / 128, Mtok / 128), 256>>>(p_gated, p_wq_o, x, p_x2,
                                                         Mtok, Dn, Dn);

    // 6) h2 = rmsnorm(x2, norm2_w)
    rmsnorm_kernel<<<Mtok, 256>>>(p_x2, n2w, p_h);

    // 7) m = gelu(h2 @ Wq_mi^T)   (16384 x 2048, K=1024)
    sgemm_kernel<2><<<dim3(MHn / 128, Mtok / 128), 256>>>(p_h, p_wq_mi, nullptr, p_qkv,
                                                          Mtok, MHn, Dn);

    // 8) out = x2 + m @ Wq_mo^T   (16384 x 1024, K=2048)
    sgemm_kernel<1><<<dim3(Dn / 128, Mtok / 128), 256>>>(p_qkv, p_wq_mo, p_x2, out,
                                                         Mtok, Dn, MHn);
}

// round 2
// speedup vs baseline: 3.9789x; 3.9789x over previous
#include <cuda_runtime.h>
#include <cuda_bf16.h>
#include <math.h>
#include <stdint.h>

// Problem constants
#define Bsz   4
#define Tn    4096
#define Dn    1024
#define Hn    8
#define HDn   128
#define MHn   2048
#define Mtok  (Bsz * Tn)          // 16384 tokens
#define EPSv  1e-6f

// GEMM tile config
#define BM 128
#define BN 128
#define BKh 32          // K-halves per tile iteration
#define ASTRIDE 40      // smem row stride in halves (80B) -> conflict-free ldmatrix

// ---------------------------------------------------------------------------
// Device-global scratch (no cudaMalloc allowed)
// Weights stored as exact-integer bf16, duplicated along K for hi/lo split.
// ---------------------------------------------------------------------------
__device__ __nv_bfloat16 g_wq_in[(size_t)MHn * 2 * Dn];    // (2048, 2048)
__device__ __nv_bfloat16 g_wq_o [(size_t)Dn  * 2 * Dn];    // (1024, 2048)
__device__ __nv_bfloat16 g_wq_mi[(size_t)MHn * 2 * Dn];    // (2048, 2048)
__device__ __nv_bfloat16 g_wq_mo[(size_t)Dn  * 2 * MHn];   // (1024, 4096)
__device__ float g_sc_in[MHn];
__device__ float g_sc_o [Dn];
__device__ float g_sc_mi[MHn];
__device__ float g_sc_mo[Dn];
__device__ __nv_bfloat16 g_h    [(size_t)Mtok * 2 * Dn];   // hi/lo rmsnorm out
__device__ float         g_qkv  [(size_t)Mtok * MHn];      // qkv fp32
__device__ __nv_bfloat16 g_gated[(size_t)Mtok * 2 * Dn];   // hi/lo gated
__device__ __nv_bfloat16 g_act  [(size_t)Mtok * 2 * MHn];  // hi/lo gelu out
__device__ float         g_x2   [(size_t)Mtok * Dn];       // post-attn residual

// ---------------------------------------------------------------------------
// PTX helpers
// ---------------------------------------------------------------------------
__device__ __forceinline__ uint32_t smem_u32(const void* p) {
    return (uint32_t)__cvta_generic_to_shared(p);
}
__device__ __forceinline__ void cpa16(uint32_t s, const void* g) {
    asm volatile("cp.async.cg.shared.global [%0], [%1], 16;" :: "r"(s), "l"(g));
}
__device__ __forceinline__ void cpa_commit() {
    asm volatile("cp.async.commit_group;");
}
__device__ __forceinline__ void cpa_wait0() {
    asm volatile("cp.async.wait_group 0;");
}
__device__ __forceinline__ void ldsm4(uint32_t& r0, uint32_t& r1, uint32_t& r2, uint32_t& r3,
                                      uint32_t addr) {
    asm volatile("ldmatrix.sync.aligned.m8n8.x4.shared.b16 {%0,%1,%2,%3}, [%4];"
                 : "=r"(r0), "=r"(r1), "=r"(r2), "=r"(r3) : "r"(addr));
}
__device__ __forceinline__ void mma16816(float* c, uint32_t a0, uint32_t a1, uint32_t a2,
                                         uint32_t a3, uint32_t b0, uint32_t b1) {
    asm volatile("mma.sync.aligned.m16n8k16.row.col.f32.bf16.bf16.f32 "
                 "{%0,%1,%2,%3}, {%4,%5,%6,%7}, {%8,%9}, {%0,%1,%2,%3};"
                 : "+f"(c[0]), "+f"(c[1]), "+f"(c[2]), "+f"(c[3])
                 : "r"(a0), "r"(a1), "r"(a2), "r"(a3), "r"(b0), "r"(b1));
}

__device__ __forceinline__ __nv_bfloat162 hilo_pair(float v) {
    __nv_bfloat16 hi = __float2bfloat16_rn(v);
    __nv_bfloat16 lo = __float2bfloat16_rn(v - __bfloat162float(hi));
    __nv_bfloat162 p; p.x = hi; p.y = lo; return p;
}

// ---------------------------------------------------------------------------
// Per-row int8 fake quantization -> exact-integer bf16, duplicated along K.
// wq2[n, 2k] = wq2[n, 2k+1] = bf16(round(w/scale));  scales[n] = scale
// ---------------------------------------------------------------------------
__global__ void quantize_rows_kernel(const float* __restrict__ w,
                                     __nv_bfloat16* __restrict__ wq2,
                                     float* __restrict__ scales, int C) {
    int row = blockIdx.x;
    const float* wr = w + (size_t)row * C;
    float m = 0.f;
    for (int i = threadIdx.x; i < C; i += blockDim.x)
        m = fmaxf(m, fabsf(wr[i]));
    __shared__ float sh[32];
    int lane = threadIdx.x & 31, wid = threadIdx.x >> 5;
#pragma unroll
    for (int o = 16; o; o >>= 1) m = fmaxf(m, __shfl_xor_sync(0xffffffffu, m, o));
    if (lane == 0) sh[wid] = m;
    __syncthreads();
    if (wid == 0) {
        float v = (lane < (blockDim.x >> 5)) ? sh[lane] : 0.f;
#pragma unroll
        for (int o = 16; o; o >>= 1) v = fmaxf(v, __shfl_xor_sync(0xffffffffu, v, o));
        if (lane == 0) sh[0] = v;
    }
    __syncthreads();
    float scale = fmaxf(sh[0] * (1.0f / 127.0f), 1e-8f);
    if (threadIdx.x == 0) scales[row] = scale;
    for (int i = threadIdx.x; i < C; i += blockDim.x) {
        float q = rintf(wr[i] / scale);                 // integer, |q|<=127, exact in bf16
        __nv_bfloat16 qb = __float2bfloat16_rn(q);
        __nv_bfloat162 p; p.x = qb; p.y = qb;
        *(__nv_bfloat162*)&wq2[(size_t)row * 2 * C + 2 * i] = p;
    }
}

// ---------------------------------------------------------------------------
// RMSNorm -> hi/lo interleaved bf16, row stride 2*Dn
// ---------------------------------------------------------------------------
__global__ void rmsnorm_kernel(const float* __restrict__ x,
                               const float* __restrict__ w,
                               __nv_bfloat16* __restrict__ out) {
    int row = blockIdx.x;
    const float* xr = x + (size_t)row * Dn;
    float ss = 0.f;
    for (int i = threadIdx.x; i < Dn; i += blockDim.x) {
        float v = xr[i];
        ss += v * v;
    }
    __shared__ float sh[32];
    int lane = threadIdx.x & 31, wid = threadIdx.x >> 5;
#pragma unroll
    for (int o = 16; o; o >>= 1) ss += __shfl_xor_sync(0xffffffffu, ss, o);
    if (lane == 0) sh[wid] = ss;
    __syncthreads();
    if (wid == 0) {
        float v = (lane < (blockDim.x >> 5)) ? sh[lane] : 0.f;
#pragma unroll
        for (int o = 16; o; o >>= 1) v += __shfl_xor_sync(0xffffffffu, v, o);
        if (lane == 0) sh[0] = v;
    }
    __syncthreads();
    float inv = rsqrtf(sh[0] * (1.0f / Dn) + EPSv);
    for (int i = threadIdx.x; i < Dn; i += blockDim.x) {
        float v = xr[i] * inv * w[i];
        *(__nv_bfloat162*)&out[(size_t)row * 2 * Dn + 2 * i] = hilo_pair(v);
    }
}

// ---------------------------------------------------------------------------
// Causal exp-filter conv = linear recurrence, chunk-parallel with warm-up.
// alpha^512 = e^-51 -> warm-up truncation error ~1e-22 (negligible).
// Output: gated hi/lo bf16, row stride 2*Dn.
// grid: 4(colgrp) x 4(batch) x 8(chunk) = 128 blocks, 256 threads.
// ---------------------------------------------------------------------------
#define SCH 512
__global__ void scan_gate_kernel(const float* __restrict__ qkv,
                                 const float* __restrict__ filt,   // (T, H)
                                 __nv_bfloat16* __restrict__ gated) {
    int tid = threadIdx.x;
    int chunk = blockIdx.x & 7;
    int b = (blockIdx.x >> 3) & 3;
    int cg = blockIdx.x >> 5;
    int c = cg * 256 + tid;
    int h = c >> 7;
    float f0 = filt[h];
    float alpha = filt[Hn + h] / f0;
    const float* base = qkv + (size_t)b * Tn * MHn;
    __nv_bfloat16* ob = gated + (size_t)b * Tn * 2 * Dn;
    float y = 0.f;
    int t0 = chunk * SCH;
    if (chunk) {
#pragma unroll 4
        for (int t = t0 - SCH; t < t0; ++t)
            y = fmaf(alpha, y, base[(size_t)t * MHn + c]);
    }
#pragma unroll 4
    for (int t = t0; t < t0 + SCH; ++t) {
        float s = base[(size_t)t * MHn + c];
        float g = base[(size_t)t * MHn + Dn + c];
        y = fmaf(alpha, y, s);
        float sig = 1.0f / (1.0f + expf(-g));
        float v = (f0 * y) * (g * sig);
        *(__nv_bfloat162*)&ob[(size_t)t * 2 * Dn + 2 * c] = hilo_pair(v);
    }
}

// ---------------------------------------------------------------------------
// bf16 tensor-core GEMM: acc[m,n] = sum_k2 A[m,k2] * Bw[n,k2]
// result v = acc * scales[n]; epilogues:
//   EPI 0: Cf[m,n] = v
//   EPI 1: Cf[m,n] = v + Add[m,n]
//   EPI 2: Cb[m, 2n..2n+1] = hilo(gelu(v))   (row stride 2N)
// 128x128x32 tile, 256 threads (8 warps: 4m x 2n), mma.m16n8k16, cp.async 2-stage.
// ---------------------------------------------------------------------------
template <int EPI>
__global__ __launch_bounds__(256)
void mma_gemm(const __nv_bfloat16* __restrict__ A, const __nv_bfloat16* __restrict__ Bw,
              const float* __restrict__ scales, const float* __restrict__ Add,
              float* __restrict__ Cf, __nv_bfloat16* __restrict__ Cb,
              int M, int N, int K2) {
    __shared__ __nv_bfloat16 sA[2][BM * ASTRIDE];
    __shared__ __nv_bfloat16 sB[2][BN * ASTRIDE];

    int tid = threadIdx.x;
    int bm = blockIdx.y * BM;
    int bn = blockIdx.x * BN;
    int lane = tid & 31, wid = tid >> 5;
    int wm = wid >> 1, wn = wid & 1;

    int lr = tid >> 2;          // 0..63 load row
    int lc = tid & 3;           // 16B chunk within 64B row segment

    const __nv_bfloat16* Ab = A + (size_t)(bm + lr) * K2 + lc * 8;
    const __nv_bfloat16* Bb = Bw + (size_t)(bn + lr) * K2 + lc * 8;
    uint32_t sA0 = smem_u32(&sA[0][0]);
    uint32_t sB0 = smem_u32(&sB[0][0]);
    const uint32_t bufStride = BM * ASTRIDE * 2;  // bytes
    uint32_t sAw = sA0 + (lr * ASTRIDE + lc * 8) * 2;
    uint32_t sBw = sB0 + (lr * ASTRIDE + lc * 8) * 2;
    const uint32_t rowOfs64 = 64 * ASTRIDE * 2;

    float c[2][8][4];
#pragma unroll
    for (int i = 0; i < 2; ++i)
#pragma unroll
        for (int j = 0; j < 8; ++j)
#pragma unroll
            for (int l = 0; l < 4; ++l) c[i][j][l] = 0.f;

    int KT = K2 / BKh;

    // prologue: load tile 0 into buffer 0
    cpa16(sAw, Ab);
    cpa16(sAw + rowOfs64, Ab + (size_t)64 * K2);
    cpa16(sBw, Bb);
    cpa16(sBw + rowOfs64, Bb + (size_t)64 * K2);
    cpa_commit();

    for (int kt = 0; kt < KT; ++kt) {
        int buf = kt & 1;
        cpa_wait0();
        __syncthreads();

        if (kt + 1 < KT) {
            int nb = buf ^ 1;
            const __nv_bfloat16* ag = Ab + (kt + 1) * BKh;
            const __nv_bfloat16* bg = Bb + (kt + 1) * BKh;
            cpa16(sAw + nb * bufStride, ag);
            cpa16(sAw + nb * bufStride + rowOfs64, ag + (size_t)64 * K2);
            cpa16(sBw + nb * bufStride, bg);
            cpa16(sBw + nb * bufStride + rowOfs64, bg + (size_t)64 * K2);
            cpa_commit();
        }

        uint32_t aBase = sA0 + buf * bufStride;
        uint32_t bBase = sB0 + buf * bufStride;
#pragma unroll
        for (int ks = 0; ks < 2; ++ks) {
            uint32_t a[2][4];
#pragma unroll
            for (int mt = 0; mt < 2; ++mt) {
                int row = wm * 32 + mt * 16 + (lane & 15);
                int col = ks * 16 + (lane >> 4) * 8;
                ldsm4(a[mt][0], a[mt][1], a[mt][2], a[mt][3],
                      aBase + (row * ASTRIDE + col) * 2);
            }
            uint32_t b[4][4];
#pragma unroll
            for (int p = 0; p < 4; ++p) {
                int nrow = wn * 64 + p * 16 + (lane & 7) + ((lane >> 4) << 3);
                int col = ks * 16 + ((lane >> 3) & 1) * 8;
                ldsm4(b[p][0], b[p][1], b[p][2], b[p][3],
                      bBase + (nrow * ASTRIDE + col) * 2);
            }
#pragma unroll
            for (int mt = 0; mt < 2; ++mt)
#pragma unroll
                for (int nt = 0; nt < 8; ++nt)
                    mma16816(c[mt][nt], a[mt][0], a[mt][1], a[mt][2], a[mt][3],
                             b[nt >> 1][(nt & 1) * 2], b[nt >> 1][(nt & 1) * 2 + 1]);
        }
        __syncthreads();
    }

    // Epilogue
#pragma unroll
    for (int mt = 0; mt < 2; ++mt) {
#pragma unroll
        for (int nt = 0; nt < 8; ++nt) {
            int r0 = bm + wm * 32 + mt * 16 + (lane >> 2);
            int col = bn + wn * 64 + nt * 8 + (lane & 3) * 2;
            float s0 = __ldg(&scales[col]);
            float s1 = __ldg(&scales[col + 1]);
#pragma unroll
            for (int half = 0; half < 2; ++half) {
                int row = r0 + half * 8;
                float v0 = c[mt][nt][half * 2 + 0] * s0;
                float v1 = c[mt][nt][half * 2 + 1] * s1;
                if (EPI == 0) {
                    float2 o = {v0, v1};
                    *(float2*)&Cf[(size_t)row * N + col] = o;
                } else if (EPI == 1) {
                    float2 r = *(const float2*)&Add[(size_t)row * N + col];
                    float2 o = {v0 + r.x, v1 + r.y};
                    *(float2*)&Cf[(size_t)row * N + col] = o;
                } else {
                    float g0 = 0.5f * v0 * (1.0f + erff(v0 * 0.70710678118654752440f));
                    float g1 = 0.5f * v1 * (1.0f + erff(v1 * 0.70710678118654752440f));
                    __nv_bfloat162 p0 = hilo_pair(g0);
                    __nv_bfloat162 p1 = hilo_pair(g1);
                    uint2 o;
                    o.x = *(uint32_t*)&p0;
                    o.y = *(uint32_t*)&p1;
                    *(uint2*)&Cb[(size_t)row * 2 * N + 2 * col] = o;
                }
            }
        }
    }
}

// ---------------------------------------------------------------------------
// Launch
// ---------------------------------------------------------------------------
extern "C" void kernel_launch(void* const* d_in, const int* in_sizes, int n_in,
                              void* d_out, int out_size) {
    (void)in_sizes; (void)n_in; (void)out_size;
    const float* x    = (const float*)d_in[0];
    const float* n1w  = (const float*)d_in[1];
    const float* n2w  = (const float*)d_in[2];
    const float* w_in = (const float*)d_in[3];
    const float* w_o  = (const float*)d_in[4];
    const float* w_mi = (const float*)d_in[5];
    const float* w_mo = (const float*)d_in[6];
    const float* filt = (const float*)d_in[7];
    float* out = (float*)d_out;

    __nv_bfloat16 *p_wq_in, *p_wq_o, *p_wq_mi, *p_wq_mo, *p_h, *p_gated, *p_act;
    float *p_sc_in, *p_sc_o, *p_sc_mi, *p_sc_mo, *p_qkv, *p_x2;
    cudaGetSymbolAddress((void**)&p_wq_in, g_wq_in);
    cudaGetSymbolAddress((void**)&p_wq_o,  g_wq_o);
    cudaGetSymbolAddress((void**)&p_wq_mi, g_wq_mi);
    cudaGetSymbolAddress((void**)&p_wq_mo, g_wq_mo);
    cudaGetSymbolAddress((void**)&p_sc_in, g_sc_in);
    cudaGetSymbolAddress((void**)&p_sc_o,  g_sc_o);
    cudaGetSymbolAddress((void**)&p_sc_mi, g_sc_mi);
    cudaGetSymbolAddress((void**)&p_sc_mo, g_sc_mo);
    cudaGetSymbolAddress((void**)&p_h,     g_h);
    cudaGetSymbolAddress((void**)&p_qkv,   g_qkv);
    cudaGetSymbolAddress((void**)&p_gated, g_gated);
    cudaGetSymbolAddress((void**)&p_act,   g_act);
    cudaGetSymbolAddress((void**)&p_x2,    g_x2);

    // 1) quantize weights -> exact bf16 integers (duplicated along K) + scales
    quantize_rows_kernel<<<MHn, 256>>>(w_in, p_wq_in, p_sc_in, Dn);
    quantize_rows_kernel<<<Dn,  256>>>(w_o,  p_wq_o,  p_sc_o,  Dn);
    quantize_rows_kernel<<<MHn, 256>>>(w_mi, p_wq_mi, p_sc_mi, Dn);
    quantize_rows_kernel<<<Dn,  256>>>(w_mo, p_wq_mo, p_sc_mo, MHn);

    // 2) h = rmsnorm(x, norm1_w) -> hi/lo bf16
    rmsnorm_kernel<<<Mtok, 256>>>(x, n1w, p_h);

    // 3) qkv = h @ Wq_in^T (fp32 out)
    mma_gemm<0><<<dim3(MHn / BN, Mtok / BM), 256>>>(p_h, p_wq_in, p_sc_in, nullptr,
                                                    p_qkv, nullptr, Mtok, MHn, 2 * Dn);

    // 4) causal conv recurrence + SiLU gate -> hi/lo bf16
    scan_gate_kernel<<<128, 256>>>(p_qkv, filt, p_gated);

    // 5) x2 = x + gated @ Wq_o^T
    mma_gemm<1><<<dim3(Dn / BN, Mtok / BM), 256>>>(p_gated, p_wq_o, p_sc_o, x,
                                                   p_x2, nullptr, Mtok, Dn, 2 * Dn);

    // 6) h2 = rmsnorm(x2, norm2_w) -> hi/lo bf16
    rmsnorm_kernel<<<Mtok, 256>>>(p_x2, n2w, p_h);

    // 7) m = gelu(h2 @ Wq_mi^T) -> hi/lo bf16
    mma_gemm<2><<<dim3(MHn / BN, Mtok / BM), 256>>>(p_h, p_wq_mi, p_sc_mi, nullptr,
                                                    nullptr, p_act, Mtok, MHn, 2 * Dn);

    // 8) out = x2 + m @ Wq_mo^T
    mma_gemm<1><<<dim3(Dn / BN, Mtok / BM), 256>>>(p_act, p_wq_mo, p_sc_mo, p_x2,
                                                   out, nullptr, Mtok, Dn, 2 * MHn);
}

// round 4
// speedup vs baseline: 5.9296x; 1.4903x over previous
#include <cuda_runtime.h>
#include <cuda_fp16.h>
#include <math.h>
#include <stdint.h>

// Problem constants
#define Bsz   4
#define Tn    4096
#define Dn    1024
#define Hn    8
#define MHn   2048
#define Mtok  (Bsz * Tn)          // 16384 tokens
#define EPSv  1e-6f

// GEMM tile config
#define BM 128
#define BN 128
#define BKh 32          // K-halves per stage
#define NST 4           // pipeline stages
#define ASTRIDE 40      // smem row stride in halves -> conflict-free ldmatrix
#define STAGE_A  (BM * ASTRIDE * 2)             // 10240 B
#define STAGE_B  (BN * ASTRIDE * 2)             // 10240 B
#define STAGEB   (STAGE_A + STAGE_B)            // 20480 B
#define SMEM_MMA (NST * STAGEB)                 // 81920 B

// ---------------------------------------------------------------------------
// Device-global scratch (no cudaMalloc).  Weights: exact-integer fp16 [N,K].
// Activations: plain row-major fp16.
// ---------------------------------------------------------------------------
__device__ __half g_wq_in[(size_t)MHn * Dn];
__device__ __half g_wq_o [(size_t)Dn  * Dn];
__device__ __half g_wq_mi[(size_t)MHn * Dn];
__device__ __half g_wq_mo[(size_t)Dn  * MHn];
__device__ float g_sc_in[MHn];
__device__ float g_sc_o [Dn];
__device__ float g_sc_mi[MHn];
__device__ float g_sc_mo[Dn];
__device__ __half g_h    [(size_t)Mtok * Dn];    // rmsnorm out (reused for h2)
__device__ float  g_qkv  [(size_t)Mtok * MHn];   // qkv fp32
__device__ __half g_gated[(size_t)Mtok * Dn];    // gated fp16
__device__ __half g_act  [(size_t)Mtok * MHn];   // gelu out fp16
__device__ float  g_x2   [(size_t)Mtok * Dn];    // post-attn residual

// ---------------------------------------------------------------------------
// PTX helpers
// ---------------------------------------------------------------------------
__device__ __forceinline__ uint32_t smem_u32(const void* p) {
    return (uint32_t)__cvta_generic_to_shared(p);
}
__device__ __forceinline__ void cpa16(uint32_t s, const void* g) {
    asm volatile("cp.async.cg.shared.global [%0], [%1], 16;" :: "r"(s), "l"(g));
}
__device__ __forceinline__ void cpa_commit() {
    asm volatile("cp.async.commit_group;");
}
__device__ __forceinline__ void ldsm4(uint32_t& r0, uint32_t& r1, uint32_t& r2, uint32_t& r3,
                                      uint32_t addr) {
    asm volatile("ldmatrix.sync.aligned.m8n8.x4.shared.b16 {%0,%1,%2,%3}, [%4];"
                 : "=r"(r0), "=r"(r1), "=r"(r2), "=r"(r3) : "r"(addr));
}
__device__ __forceinline__ void mma16816(float* c, uint32_t a0, uint32_t a1, uint32_t a2,
                                         uint32_t a3, uint32_t b0, uint32_t b1) {
    asm volatile("mma.sync.aligned.m16n8k16.row.col.f32.f16.f16.f32 "
                 "{%0,%1,%2,%3}, {%4,%5,%6,%7}, {%8,%9}, {%0,%1,%2,%3};"
                 : "+f"(c[0]), "+f"(c[1]), "+f"(c[2]), "+f"(c[3])
                 : "r"(a0), "r"(a1), "r"(a2), "r"(a3), "r"(b0), "r"(b1));
}

// ---------------------------------------------------------------------------
// Quantize: wq[n,k] = fp16(round(w/scale))  (exact integers), scales[n]=scale
// ---------------------------------------------------------------------------
__global__ void quantize_rows_kernel(const float* __restrict__ w,
                                     __half* __restrict__ wq,
                                     float* __restrict__ scales, int C) {
    int row = blockIdx.x;
    const float* wr = w + (size_t)row * C;
    float m = 0.f;
    for (int i = threadIdx.x; i < C; i += blockDim.x)
        m = fmaxf(m, fabsf(wr[i]));
    __shared__ float sh[32];
    int lane = threadIdx.x & 31, wid = threadIdx.x >> 5;
#pragma unroll
    for (int o = 16; o; o >>= 1) m = fmaxf(m, __shfl_xor_sync(0xffffffffu, m, o));
    if (lane == 0) sh[wid] = m;
    __syncthreads();
    if (wid == 0) {
        float v = (lane < (blockDim.x >> 5)) ? sh[lane] : 0.f;
#pragma unroll
        for (int o = 16; o; o >>= 1) v = fmaxf(v, __shfl_xor_sync(0xffffffffu, v, o));
        if (lane == 0) sh[0] = v;
    }
    __syncthreads();
    float scale = fmaxf(sh[0] * (1.0f / 127.0f), 1e-8f);
    if (threadIdx.x == 0) scales[row] = scale;
    for (int i = threadIdx.x; i < C; i += blockDim.x)
        wq[(size_t)row * C + i] = __float2half_rn(rintf(wr[i] / scale));
}

// ---------------------------------------------------------------------------
// RMSNorm -> fp16
// ---------------------------------------------------------------------------
__global__ void rmsnorm_kernel(const float* __restrict__ x,
                               const float* __restrict__ w,
                               __half* __restrict__ out) {
    int row = blockIdx.x;
    const float* xr = x + (size_t)row * Dn;
    float ss = 0.f;
    for (int i = threadIdx.x; i < Dn; i += blockDim.x) {
        float v = xr[i];
        ss += v * v;
    }
    __shared__ float sh[32];
    int lane = threadIdx.x & 31, wid = threadIdx.x >> 5;
#pragma unroll
    for (int o = 16; o; o >>= 1) ss += __shfl_xor_sync(0xffffffffu, ss, o);
    if (lane == 0) sh[wid] = ss;
    __syncthreads();
    if (wid == 0) {
        float v = (lane < (blockDim.x >> 5)) ? sh[lane] : 0.f;
#pragma unroll
        for (int o = 16; o; o >>= 1) v += __shfl_xor_sync(0xffffffffu, v, o);
        if (lane == 0) sh[0] = v;
    }
    __syncthreads();
    float inv = rsqrtf(sh[0] * (1.0f / Dn) + EPSv);
    for (int i = threadIdx.x; i < Dn; i += blockDim.x)
        out[(size_t)row * Dn + i] = __float2half_rn(xr[i] * inv * w[i]);
}

// ---------------------------------------------------------------------------
// Causal exp-filter conv (linear recurrence, chunked w/ 512-step warmup) + SiLU
// ---------------------------------------------------------------------------
#define SCH 512
__global__ void scan_gate_kernel(const float* __restrict__ qkv,
                                 const float* __restrict__ filt,
                                 __half* __restrict__ gated) {
    int tid = threadIdx.x;
    int chunk = blockIdx.x & 7;
    int b = (blockIdx.x >> 3) & 3;
    int cg = blockIdx.x >> 5;
    int c = cg * 256 + tid;
    int h = c >> 7;
    float f0 = filt[h];
    float alpha = filt[Hn + h] / f0;
    const float* base = qkv + (size_t)b * Tn * MHn;
    __half* ob = gated + (size_t)b * Tn * Dn;
    float y = 0.f;
    int t0 = chunk * SCH;
    if (chunk) {
#pragma unroll 4
        for (int t = t0 - SCH; t < t0; ++t)
            y = fmaf(alpha, y, base[(size_t)t * MHn + c]);
    }
#pragma unroll 2
    for (int t = t0; t < t0 + SCH; ++t) {
        float s = base[(size_t)t * MHn + c];
        float g = base[(size_t)t * MHn + Dn + c];
        y = fmaf(alpha, y, s);
        float sig = 1.0f / (1.0f + expf(-g));
        ob[(size_t)t * Dn + c] = __float2half_rn((f0 * y) * (g * sig));
    }
}

// ---------------------------------------------------------------------------
// fp16 tensor-core GEMM: v[m,n] = (sum_k A[m,k]*W[n,k]) * scales[n]
//   EPI 0: Cf = v     EPI 1: Cf = v + Add     EPI 2: Ch = fp16(gelu(v))
// 128x128 tile, BK=32, 256 thr (8 warps 4m x 2n), 4-stage cp.async pipeline.
// ---------------------------------------------------------------------------
template <int EPI>
__global__ __launch_bounds__(256)
void mma_gemm(const __half* __restrict__ A, const __half* __restrict__ W,
              const float* __restrict__ scales, const float* __restrict__ Add,
              float* __restrict__ Cf, __half* __restrict__ Ch,
              int M, int N, int K) {
    extern __shared__ char smem[];
    uint32_t s0 = smem_u32(smem);

    int tid = threadIdx.x;
    int bm = blockIdx.y * BM;
    int bn = blockIdx.x * BN;
    int lane = tid & 31, wid = tid >> 5;
    int wm = wid >> 1, wn = wid & 1;

    int lr = tid >> 2;          // 0..63 load row
    int lc = tid & 3;           // 16B chunk within 64B row

    const __half* Ab = A + (size_t)(bm + lr) * K + lc * 8;
    const __half* Bb = W + (size_t)(bn + lr) * K + lc * 8;
    uint32_t aoff = (uint32_t)(lr * ASTRIDE + lc * 8) * 2;
    const uint32_t rowOfs64 = 64 * ASTRIDE * 2;

    auto load_tile = [&](int kt) {
        uint32_t tb = s0 + (kt & (NST - 1)) * STAGEB;
        const __half* ag = Ab + (size_t)kt * BKh;
        const __half* bg = Bb + (size_t)kt * BKh;
        cpa16(tb + aoff, ag);
        cpa16(tb + aoff + rowOfs64, ag + (size_t)64 * K);
        cpa16(tb + STAGE_A + aoff, bg);
        cpa16(tb + STAGE_A + aoff + rowOfs64, bg + (size_t)64 * K);
        cpa_commit();
    };

    float c[2][8][4];
#pragma unroll
    for (int i = 0; i < 2; ++i)
#pragma unroll
        for (int j = 0; j < 8; ++j)
#pragma unroll
            for (int l = 0; l < 4; ++l) c[i][j][l] = 0.f;

    int KT = K / BKh;
    load_tile(0);
    load_tile(1);
    load_tile(2);

    for (int kt = 0; kt < KT; ++kt) {
        if (kt < KT - 2)      asm volatile("cp.async.wait_group 2;");
        else if (kt == KT - 2) asm volatile("cp.async.wait_group 1;");
        else                   asm volatile("cp.async.wait_group 0;");
        __syncthreads();

        if (kt + 3 < KT) load_tile(kt + 3);

        uint32_t aBase = s0 + (kt & (NST - 1)) * STAGEB;
        uint32_t bBase = aBase + STAGE_A;
#pragma unroll
        for (int ks = 0; ks < 2; ++ks) {
            uint32_t a[2][4];
#pragma unroll
            for (int mt = 0; mt < 2; ++mt) {
                int row = wm * 32 + mt * 16 + (lane & 15);
                int col = ks * 16 + (lane >> 4) * 8;
                ldsm4(a[mt][0], a[mt][1], a[mt][2], a[mt][3],
                      aBase + (row * ASTRIDE + col) * 2);
            }
            uint32_t b[4][4];
#pragma unroll
            for (int p = 0; p < 4; ++p) {
                int nrow = wn * 64 + p * 16 + (lane & 7) + ((lane >> 4) << 3);
                int col = ks * 16 + ((lane >> 3) & 1) * 8;
                ldsm4(b[p][0], b[p][1], b[p][2], b[p][3],
                      bBase + (nrow * ASTRIDE + col) * 2);
            }
#pragma unroll
            for (int mt = 0; mt < 2; ++mt)
#pragma unroll
                for (int nt = 0; nt < 8; ++nt)
                    mma16816(c[mt][nt], a[mt][0], a[mt][1], a[mt][2], a[mt][3],
                             b[nt >> 1][(nt & 1) * 2], b[nt >> 1][(nt & 1) * 2 + 1]);
        }
        __syncthreads();
    }

    // Epilogue
#pragma unroll
    for (int mt = 0; mt < 2; ++mt) {
#pragma unroll
        for (int nt = 0; nt < 8; ++nt) {
            int r0 = bm + wm * 32 + mt * 16 + (lane >> 2);
            int col = bn + wn * 64 + nt * 8 + (lane & 3) * 2;
            float sc0 = __ldg(&scales[col]);
            float sc1 = __ldg(&scales[col + 1]);
#pragma unroll
            for (int half = 0; half < 2; ++half) {
                int row = r0 + half * 8;
                float v0 = c[mt][nt][half * 2 + 0] * sc0;
                float v1 = c[mt][nt][half * 2 + 1] * sc1;
                if (EPI == 0) {
                    float2 o = {v0, v1};
                    *(float2*)&Cf[(size_t)row * N + col] = o;
                } else if (EPI == 1) {
                    float2 r = *(const float2*)&Add[(size_t)row * N + col];
                    float2 o = {v0 + r.x, v1 + r.y};
                    *(float2*)&Cf[(size_t)row * N + col] = o;
                } else {
                    float g0 = 0.5f * v0 * (1.0f + erff(v0 * 0.70710678118654752440f));
                    float g1 = 0.5f * v1 * (1.0f + erff(v1 * 0.70710678118654752440f));
                    __half2 o = {__float2half_rn(g0), __float2half_rn(g1)};
                    *(__half2*)&Ch[(size_t)row * N + col] = o;
                }
            }
        }
    }
}

// ---------------------------------------------------------------------------
// Launch
// ---------------------------------------------------------------------------
extern "C" void kernel_launch(void* const* d_in, const int* in_sizes, int n_in,
                              void* d_out, int out_size) {
    (void)in_sizes; (void)n_in; (void)out_size;
    const float* x    = (const float*)d_in[0];
    const float* n1w  = (const float*)d_in[1];
    const float* n2w  = (const float*)d_in[2];
    const float* w_in = (const float*)d_in[3];
    const float* w_o  = (const float*)d_in[4];
    const float* w_mi = (const float*)d_in[5];
    const float* w_mo = (const float*)d_in[6];
    const float* filt = (const float*)d_in[7];
    float* out = (float*)d_out;

    __half *p_wq_in, *p_wq_o, *p_wq_mi, *p_wq_mo, *p_h, *p_gated, *p_act;
    float *p_sc_in, *p_sc_o, *p_sc_mi, *p_sc_mo, *p_qkv, *p_x2;
    cudaGetSymbolAddress((void**)&p_wq_in, g_wq_in);
    cudaGetSymbolAddress((void**)&p_wq_o,  g_wq_o);
    cudaGetSymbolAddress((void**)&p_wq_mi, g_wq_mi);
    cudaGetSymbolAddress((void**)&p_wq_mo, g_wq_mo);
    cudaGetSymbolAddress((void**)&p_sc_in, g_sc_in);
    cudaGetSymbolAddress((void**)&p_sc_o,  g_sc_o);
    cudaGetSymbolAddress((void**)&p_sc_mi, g_sc_mi);
    cudaGetSymbolAddress((void**)&p_sc_mo, g_sc_mo);
    cudaGetSymbolAddress((void**)&p_h,     g_h);
    cudaGetSymbolAddress((void**)&p_qkv,   g_qkv);
    cudaGetSymbolAddress((void**)&p_gated, g_gated);
    cudaGetSymbolAddress((void**)&p_act,   g_act);
    cudaGetSymbolAddress((void**)&p_x2,    g_x2);

    cudaFuncSetAttribute(mma_gemm<0>, cudaFuncAttributeMaxDynamicSharedMemorySize, SMEM_MMA);
    cudaFuncSetAttribute(mma_gemm<1>, cudaFuncAttributeMaxDynamicSharedMemorySize, SMEM_MMA);
    cudaFuncSetAttribute(mma_gemm<2>, cudaFuncAttributeMaxDynamicSharedMemorySize, SMEM_MMA);

    // 1) quantize weights -> exact fp16 integers + scales
    quantize_rows_kernel<<<MHn, 256>>>(w_in, p_wq_in, p_sc_in, Dn);
    quantize_rows_kernel<<<Dn,  256>>>(w_o,  p_wq_o,  p_sc_o,  Dn);
    quantize_rows_kernel<<<MHn, 256>>>(w_mi, p_wq_mi, p_sc_mi, Dn);
    quantize_rows_kernel<<<Dn,  256>>>(w_mo, p_wq_mo, p_sc_mo, MHn);

    // 2) h = rmsnorm(x) -> fp16
    rmsnorm_kernel<<<Mtok, 256>>>(x, n1w, p_h);

    // 3) qkv = h @ Wq_in^T (fp32 out)
    mma_gemm<0><<<dim3(MHn / BN, Mtok / BM), 256, SMEM_MMA>>>(
        p_h, p_wq_in, p_sc_in, nullptr, p_qkv, nullptr, Mtok, MHn, Dn);

    // 4) causal conv recurrence + SiLU gate -> fp16
    scan_gate_kernel<<<128, 256>>>(p_qkv, filt, p_gated);

    // 5) x2 = x + gated @ Wq_o^T
    mma_gemm<1><<<dim3(Dn / BN, Mtok / BM), 256, SMEM_MMA>>>(
        p_gated, p_wq_o, p_sc_o, x, p_x2, nullptr, Mtok, Dn, Dn);

    // 6) h2 = rmsnorm(x2) -> fp16
    rmsnorm_kernel<<<Mtok, 256>>>(p_x2, n2w, p_h);

    // 7) m = gelu(h2 @ Wq_mi^T) -> fp16
    mma_gemm<2><<<dim3(MHn / BN, Mtok / BM), 256, SMEM_MMA>>>(
        p_h, p_wq_mi, p_sc_mi, nullptr, nullptr, p_act, Mtok, MHn, Dn);

    // 8) out = x2 + m @ Wq_mo^T
    mma_gemm<1><<<dim3(Dn / BN, Mtok / BM), 256, SMEM_MMA>>>(
        p_act, p_wq_mo, p_sc_mo, p_x2, out, nullptr, Mtok, Dn, MHn);
}